// round 5
// baseline (speedup 1.0000x reference)
#include <cuda_runtime.h>
#include <cuda_bf16.h>
#include <math.h>
#include <stdint.h>

// ---------------- problem constants ----------------
#define CDIM   192
#define IMGHW  224
#define HW     (IMGHW*IMGHW)          // 50176
#define BATCH  4
#define HWC    ((size_t)CDIM*HW)
#define NWIN   3136
#define NTOK   200704                 // NWIN * 64 == BATCH*HW
#define NHEADS 6
#define OUT_MAIN ((size_t)BATCH*HWC)  // 38,535,168
#define RECON_DENOM 38535168.0

// ---------------- scratch (device globals) ----------------
__device__ __align__(16) float g_attn[OUT_MAIN/0x1p0 == 0 ? 1 : (size_t)NTOK*192];
__device__ __align__(16) float g_f2  [(size_t)NTOK*192];   // NHWC dwconv out; later fused fp32
__device__ __align__(16) float g_p   [(size_t)NTOK*192];   // fp32 p (for loss)
__device__ __align__(16) __nv_bfloat16 g_pb   [(size_t)NTOK*192];  // xT first, then pb
__device__ __align__(16) __nv_bfloat16 g_qkvb [(size_t)NTOK*576];  // f1b first, then qkv
__device__ __align__(16) __nv_bfloat16 g_hb   [(size_t)NTOK*768];
__device__ __align__(16) __nv_bfloat16 g_mb   [(size_t)NTOK*192];
__device__ __align__(16) __nv_bfloat16 g_fusedb[(size_t)NTOK*192];
__device__ __align__(16) __nv_bfloat16 g_wt_pre [192*192];
__device__ __align__(16) __nv_bfloat16 g_wt_qkv [576*192];
__device__ __align__(16) __nv_bfloat16 g_wt_g1  [768*192];
__device__ __align__(16) __nv_bfloat16 g_wt_g2  [192*768];
__device__ __align__(16) __nv_bfloat16 g_wt_proj[192*192];
__device__ __align__(16) __nv_bfloat16 g_wt_rec [192*192];
__device__ float g_loss[1];

// ---------------- HMMA m16n8k16 bf16 helper ----------------
__device__ __forceinline__ void mma_bf16(float c[4],
    uint32_t a0, uint32_t a1, uint32_t a2, uint32_t a3,
    uint32_t b0, uint32_t b1)
{
    asm volatile(
        "mma.sync.aligned.m16n8k16.row.col.f32.bf16.bf16.f32 "
        "{%0,%1,%2,%3}, {%4,%5,%6,%7}, {%8,%9}, {%0,%1,%2,%3};"
        : "+f"(c[0]), "+f"(c[1]), "+f"(c[2]), "+f"(c[3])
        : "r"(a0), "r"(a1), "r"(a2), "r"(a3), "r"(b0), "r"(b1));
}

// ---------------- HMMA GEMM ----------------
// C[M, Ntot] = A[M,K]bf16 @ BT[Ntot,K]bf16^T + fused epilogue.
// CTA tile 128 x 64, K-chunk 32, double buffered, 256 threads (8 warps 4x2).
enum { E_BIASN = 0, E_GELU = 1, E_MUL = 2, E_PROJ = 3, E_LOSS = 4 };

template<int EPI>
__global__ void __launch_bounds__(256)
hmma_gemm(const __nv_bfloat16* __restrict__ A, int lda,
          const __nv_bfloat16* __restrict__ BT, int K,
          const float* __restrict__ bias,
          float* __restrict__ Cf,
          __nv_bfloat16* __restrict__ Cb, int ldc,
          const float* __restrict__ extra,
          float* __restrict__ lossAcc)
{
    __shared__ __align__(16) __nv_bfloat16 sA[2][128][40];
    __shared__ __align__(16) __nv_bfloat16 sB[2][64][40];
    __shared__ float red[256];

    const int tid = threadIdx.x;
    const int lane = tid & 31, wid = tid >> 5;
    const int wm = wid & 3, wn = wid >> 2;

    const __nv_bfloat16* Ab = A + (size_t)(blockIdx.y * 128) * lda;
    const __nv_bfloat16* Bb = BT + (size_t)(blockIdx.x * 64) * K;

    float acc[2][4][4] = {};
    const int nk = K >> 5;

    // chunk loader: 128x32 A (512 uint4), 64x32 B (256 uint4)
    #define LOAD_CHUNK(buf, k0) do {                                          \
        _Pragma("unroll")                                                     \
        for (int it = 0; it < 2; it++) {                                      \
            int id = tid + it * 256;                                          \
            int r = id >> 2, q = id & 3;                                      \
            *(uint4*)&sA[buf][r][q * 8] =                                     \
                *(const uint4*)(Ab + (size_t)r * lda + (k0) + q * 8);         \
        }                                                                     \
        {                                                                     \
            int r = tid >> 2, q = tid & 3;                                    \
            *(uint4*)&sB[buf][r][q * 8] =                                     \
                *(const uint4*)(Bb + (size_t)r * K + (k0) + q * 8);           \
        }                                                                     \
    } while (0)

    LOAD_CHUNK(0, 0);
    __syncthreads();

    for (int kc = 0; kc < nk; kc++) {
        int b = kc & 1;
        if (kc + 1 < nk) { LOAD_CHUNK(b ^ 1, (kc + 1) * 32); }

        #pragma unroll
        for (int ks = 0; ks < 2; ks++) {
            const int kof = ks * 16 + (lane & 3) * 2;
            uint32_t af[2][4];
            #pragma unroll
            for (int mi = 0; mi < 2; mi++) {
                int r = wm * 32 + mi * 16 + (lane >> 2);
                af[mi][0] = *(const uint32_t*)&sA[b][r][kof];
                af[mi][1] = *(const uint32_t*)&sA[b][r + 8][kof];
                af[mi][2] = *(const uint32_t*)&sA[b][r][kof + 8];
                af[mi][3] = *(const uint32_t*)&sA[b][r + 8][kof + 8];
            }
            uint32_t bfr[4][2];
            #pragma unroll
            for (int ni = 0; ni < 4; ni++) {
                int n = wn * 32 + ni * 8 + (lane >> 2);
                bfr[ni][0] = *(const uint32_t*)&sB[b][n][kof];
                bfr[ni][1] = *(const uint32_t*)&sB[b][n][kof + 8];
            }
            #pragma unroll
            for (int mi = 0; mi < 2; mi++)
                #pragma unroll
                for (int ni = 0; ni < 4; ni++)
                    mma_bf16(acc[mi][ni], af[mi][0], af[mi][1], af[mi][2],
                             af[mi][3], bfr[ni][0], bfr[ni][1]);
        }
        __syncthreads();
    }
    #undef LOAD_CHUNK

    // ---------------- epilogue ----------------
    float lsum = 0.f;
    #pragma unroll
    for (int mi = 0; mi < 2; mi++) {
        #pragma unroll
        for (int ni = 0; ni < 4; ni++) {
            int r0 = blockIdx.y * 128 + wm * 32 + mi * 16 + (lane >> 2);
            int n0 = blockIdx.x * 64 + wn * 32 + ni * 8 + (lane & 3) * 2;
            float b0 = bias[n0], b1 = bias[n0 + 1];
            #pragma unroll
            for (int h = 0; h < 2; h++) {
                int r = r0 + h * 8;
                float v0 = acc[mi][ni][2 * h] + b0;
                float v1 = acc[mi][ni][2 * h + 1] + b1;
                if (EPI == E_GELU) {
                    v0 = 0.5f * v0 * (1.0f + erff(v0 * 0.70710678118654752f));
                    v1 = 0.5f * v1 * (1.0f + erff(v1 * 0.70710678118654752f));
                }
                size_t ci = (size_t)r * ldc + n0;
                if (EPI == E_MUL) { v0 *= extra[ci]; v1 *= extra[ci + 1]; }
                if (EPI == E_LOSS) {
                    lsum += fabsf(v0 - extra[ci]) + fabsf(v1 - extra[ci + 1]);
                } else {
                    __nv_bfloat162 h2 = __floats2bfloat162_rn(v0, v1);
                    *(uint32_t*)(Cb + ci) = *(uint32_t*)&h2;
                    if (EPI == E_PROJ)
                        *(float2*)(Cf + ci) = make_float2(v0, v1);
                }
            }
        }
    }

    if (EPI == E_LOSS) {
        red[tid] = lsum;
        __syncthreads();
        #pragma unroll
        for (int s = 128; s > 0; s >>= 1) {
            if (tid < s) red[tid] += red[tid + s];
            __syncthreads();
        }
        if (tid == 0) atomicAdd(lossAcc, red[0]);
    }
}

// ---------------- x transpose: NCHW fp32 -> NHWC bf16 ----------------
__global__ void __launch_bounds__(256)
transpose_x_kernel(const float* __restrict__ x, __nv_bfloat16* __restrict__ xt)
{
    __shared__ float tile[32][33];
    int s0 = blockIdx.x * 32, c0 = blockIdx.y * 32, b = blockIdx.z;
    int tx = threadIdx.x & 31, ty = threadIdx.x >> 5;   // 32 x 8
    const float* xp = x + (size_t)b * HWC;
    #pragma unroll
    for (int j = 0; j < 4; j++)
        tile[ty + 8 * j][tx] = xp[(size_t)(c0 + ty + 8 * j) * HW + s0 + tx];
    __syncthreads();
    __nv_bfloat16* op = xt + (size_t)b * HW * CDIM;
    #pragma unroll
    for (int j = 0; j < 4; j++)
        op[(size_t)(s0 + ty + 8 * j) * CDIM + c0 + tx] =
            __float2bfloat16(tile[tx][ty + 8 * j]);
}

// ---------------- depthwise 3x3, NHWC, bf16 in / fp32 out ----------------
__global__ void __launch_bounds__(192)
dwconv_nhwc_kernel(const __nv_bfloat16* __restrict__ in,
                   const float* __restrict__ w, const float* __restrict__ bias,
                   float* __restrict__ out)
{
    int c = threadIdx.x;
    int pix = blockIdx.x;
    int b = pix / HW, s = pix % HW;
    int y = s / IMGHW, xq = s % IMGHW;
    const __nv_bfloat16* ip = in + (size_t)b * HW * CDIM;
    float acc = bias[c];
    #pragma unroll
    for (int ky = 0; ky < 3; ky++) {
        int yy = y + ky - 1;
        if (yy < 0 || yy >= IMGHW) continue;
        #pragma unroll
        for (int kx = 0; kx < 3; kx++) {
            int xx = xq + kx - 1;
            if (xx < 0 || xx >= IMGHW) continue;
            acc = fmaf(__bfloat162float(ip[(size_t)(yy * IMGHW + xx) * CDIM + c]),
                       w[c * 9 + ky * 3 + kx], acc);
        }
    }
    out[(size_t)pix * CDIM + c] = acc;
}

// ---------------- LayerNorm + window partition (NHWC fp32 in) ------------
__global__ void __launch_bounds__(256)
ln_partition_kernel(const float* __restrict__ f2,
                    const float* __restrict__ lng, const float* __restrict__ lnb,
                    float* __restrict__ p, __nv_bfloat16* __restrict__ pb)
{
    extern __shared__ float tile[];    // [64][193]
    __shared__ float mu[64], rs[64];
    int win = blockIdx.x;
    int b  = win / 784;
    int wr = win % 784;
    int wy = wr / 28, wx = wr % 28;
    const float* fp = f2 + (size_t)b * HW * CDIM;

    for (int idx = threadIdx.x; idx < 64 * 192; idx += 256) {
        int t = idx / 192, c = idx % 192;
        int iy = t >> 3, ix = t & 7;
        tile[t * 193 + c] =
            fp[(size_t)((wy * 8 + iy) * IMGHW + wx * 8 + ix) * CDIM + c];
    }
    __syncthreads();
    if (threadIdx.x < 64) {
        int t = threadIdx.x;
        float s = 0.f, s2 = 0.f;
        for (int c = 0; c < 192; c++) {
            float v = tile[t * 193 + c];
            s += v; s2 = fmaf(v, v, s2);
        }
        float m = s * (1.0f / 192.0f);
        float var = s2 * (1.0f / 192.0f) - m * m;
        mu[t] = m;
        rs[t] = rsqrtf(var + 1e-6f);
    }
    __syncthreads();
    size_t pbase = (size_t)win * (64 * 192);
    for (int idx = threadIdx.x; idx < 64 * 192; idx += 256) {
        int t = idx / 192, c = idx % 192;
        float v = (tile[t * 193 + c] - mu[t]) * rs[t];
        v = fmaf(v, lng[c], lnb[c]);
        p[pbase + idx] = v;
        pb[pbase + idx] = __float2bfloat16(v);
    }
}

// ---------------- windowed multi-head attention (bf16 qkv in) ------------
__global__ void __launch_bounds__(64)
attention_kernel(const __nv_bfloat16* __restrict__ qkv, float* __restrict__ outat)
{
    __shared__ float ks[64][33];
    __shared__ float vs[64][33];
    __shared__ float ps[64][65];
    int bid = blockIdx.x;
    int win = bid / NHEADS, h = bid % NHEADS;
    size_t qbase = (size_t)win * 64 * 576;
    int hc = h * 32;

    for (int idx = threadIdx.x; idx < 64 * 32; idx += 64) {
        int t = idx >> 5, c = idx & 31;
        ks[t][c] = __bfloat162float(qkv[qbase + (size_t)t * 576 + 192 + hc + c]);
        vs[t][c] = __bfloat162float(qkv[qbase + (size_t)t * 576 + 384 + hc + c]);
    }
    __syncthreads();

    int r = threadIdx.x;
    float q[32];
    const __nv_bfloat16* qp = &qkv[qbase + (size_t)r * 576 + hc];
    #pragma unroll
    for (int c = 0; c < 32; c++) q[c] = __bfloat162float(qp[c]);

    float mx = -1e30f;
    for (int t = 0; t < 64; t++) {
        float d = 0.f;
        #pragma unroll
        for (int c = 0; c < 32; c++) d = fmaf(q[c], ks[t][c], d);
        d *= 0.17677669529663687f;
        ps[r][t] = d;
        mx = fmaxf(mx, d);
    }
    float sum = 0.f;
    for (int t = 0; t < 64; t++) {
        float e = expf(ps[r][t] - mx);
        ps[r][t] = e;
        sum += e;
    }
    float inv = 1.0f / sum;
    float* op = &outat[((size_t)win * 64 + r) * 192 + hc];
    for (int c = 0; c < 32; c++) {
        float a = 0.f;
        for (int t = 0; t < 64; t++) a = fmaf(ps[r][t], vs[t][c], a);
        op[c] = a * inv;
    }
}

// ---------------- window reverse + residual (to NCHW) ----------------
__global__ void __launch_bounds__(256)
reverse_residual_kernel(const float* __restrict__ fused,
                        const float* __restrict__ xin,
                        float* __restrict__ out)
{
    extern __shared__ float tile[];    // [64][193]
    int win = blockIdx.x;
    size_t fb = (size_t)win * (64 * 192);
    for (int idx = threadIdx.x; idx < 64 * 192; idx += 256) {
        int t = idx / 192, c = idx % 192;
        tile[t * 193 + c] = fused[fb + idx];
    }
    __syncthreads();
    int b  = win / 784;
    int wr = win % 784;
    int wy = wr / 28, wx = wr % 28;
    size_t base = (size_t)b * HWC + (size_t)(wy * 8) * IMGHW + wx * 8;
    for (int idx = threadIdx.x; idx < 64 * 192; idx += 256) {
        int c = idx >> 6, t = idx & 63;
        int iy = t >> 3, ix = t & 7;
        size_t o = base + (size_t)c * HW + iy * IMGHW + ix;
        out[o] = tile[t * 193 + c] + xin[o];
    }
}

// ---------------- weight prep ----------------
__global__ void transpose_w_kernel(const float* __restrict__ w,
                                   __nv_bfloat16* __restrict__ wt, int K, int N)
{
    int i = blockIdx.x * 256 + threadIdx.x;
    if (i < K * N) {
        int k = i / N, n = i % N;
        wt[n * K + k] = __float2bfloat16(w[i]);
    }
}
__global__ void convert_w_kernel(const float* __restrict__ w,
                                 __nv_bfloat16* __restrict__ wt, int n)
{
    int i = blockIdx.x * 256 + threadIdx.x;
    if (i < n) wt[i] = __float2bfloat16(w[i]);
}

// ---------------- tiny helpers ----------------
__global__ void zero_loss_kernel(float* l) { *l = 0.f; }
__global__ void finalize_loss_kernel(const float* l, float* out, size_t pos)
{
    out[pos] = l[0] * (float)(0.1 / RECON_DENOM);
}

// ---------------- launch ----------------
extern "C" void kernel_launch(void* const* d_in, const int* in_sizes, int n_in,
                              void* d_out, int out_size)
{
    const float* x      = (const float*)d_in[0];
    const float* w_pre1 = (const float*)d_in[1];
    const float* b_pre1 = (const float*)d_in[2];
    const float* w_dw   = (const float*)d_in[3];
    const float* b_dw   = (const float*)d_in[4];
    const float* ln_g   = (const float*)d_in[5];
    const float* ln_b   = (const float*)d_in[6];
    const float* w_qkv  = (const float*)d_in[7];
    const float* b_qkv  = (const float*)d_in[8];
    const float* w_proj = (const float*)d_in[9];
    const float* b_proj = (const float*)d_in[10];
    const float* w_g1   = (const float*)d_in[11];
    const float* b_g1   = (const float*)d_in[12];
    const float* w_g2   = (const float*)d_in[13];
    const float* b_g2   = (const float*)d_in[14];
    const float* w_rec  = (const float*)d_in[15];
    const float* b_rec  = (const float*)d_in[16];
    float* out = (float*)d_out;

    float *attn, *f2, *p, *loss;
    __nv_bfloat16 *pb, *qkvb, *hb, *mb, *fusedb;
    __nv_bfloat16 *wtpre, *wtq, *wtg1, *wtg2, *wtp, *wtr;
    cudaGetSymbolAddress((void**)&attn,  g_attn);
    cudaGetSymbolAddress((void**)&f2,    g_f2);
    cudaGetSymbolAddress((void**)&p,     g_p);
    cudaGetSymbolAddress((void**)&pb,    g_pb);
    cudaGetSymbolAddress((void**)&qkvb,  g_qkvb);
    cudaGetSymbolAddress((void**)&hb,    g_hb);
    cudaGetSymbolAddress((void**)&mb,    g_mb);
    cudaGetSymbolAddress((void**)&fusedb, g_fusedb);
    cudaGetSymbolAddress((void**)&wtpre, g_wt_pre);
    cudaGetSymbolAddress((void**)&wtq,   g_wt_qkv);
    cudaGetSymbolAddress((void**)&wtg1,  g_wt_g1);
    cudaGetSymbolAddress((void**)&wtg2,  g_wt_g2);
    cudaGetSymbolAddress((void**)&wtp,   g_wt_proj);
    cudaGetSymbolAddress((void**)&wtr,   g_wt_rec);
    cudaGetSymbolAddress((void**)&loss,  g_loss);

    __nv_bfloat16* xt  = pb;     // xT dead before pb is written (by LN)
    __nv_bfloat16* f1b = qkvb;   // f1b dead before qkv GEMM writes
    float* fused = f2;           // f2 dead after LN

    const int TILE_SMEM = 64 * 193 * 4;
    cudaFuncSetAttribute(ln_partition_kernel,
                         cudaFuncAttributeMaxDynamicSharedMemorySize, TILE_SMEM);
    cudaFuncSetAttribute(reverse_residual_kernel,
                         cudaFuncAttributeMaxDynamicSharedMemorySize, TILE_SMEM);

    zero_loss_kernel<<<1, 1>>>(loss);

    // weight prep (tiny)
    convert_w_kernel<<<(192*192 + 255) / 256, 256>>>(w_pre1, wtpre, 192*192);
    transpose_w_kernel<<<(192*576 + 255) / 256, 256>>>(w_qkv, wtq, 192, 576);
    transpose_w_kernel<<<(192*768 + 255) / 256, 256>>>(w_g1, wtg1, 192, 768);
    transpose_w_kernel<<<(768*192 + 255) / 256, 256>>>(w_g2, wtg2, 768, 192);
    transpose_w_kernel<<<(192*192 + 255) / 256, 256>>>(w_proj, wtp, 192, 192);
    transpose_w_kernel<<<(192*192 + 255) / 256, 256>>>(w_rec, wtr, 192, 192);

    // 0) x -> NHWC bf16
    transpose_x_kernel<<<dim3(HW / 32, CDIM / 32, BATCH), 256>>>(x, xt);

    // 1) 1x1 conv as HMMA GEMM: f1b[s, o] = xt[s,:] @ w_pre1[o,:]^T + b
    hmma_gemm<E_BIASN><<<dim3(3, NTOK / 128), 256>>>(
        xt, 192, wtpre, 192, b_pre1, nullptr, f1b, 192, nullptr, nullptr);

    // 2) depthwise 3x3 (NHWC)
    dwconv_nhwc_kernel<<<NTOK, 192>>>(f1b, w_dw, b_dw, f2);

    // 3) LN + window partition -> p (fp32 + bf16)
    ln_partition_kernel<<<NWIN, 256, TILE_SMEM>>>(f2, ln_g, ln_b, p, pb);

    // 4) qkv = p @ w_qkv + b
    hmma_gemm<E_BIASN><<<dim3(9, NTOK / 128), 256>>>(
        pb, 192, wtq, 192, b_qkv, nullptr, qkvb, 576, nullptr, nullptr);

    // 5) windowed attention -> attn fp32
    attention_kernel<<<NWIN * NHEADS, 64>>>(qkvb, attn);

    // 6) h = gelu(v @ w_g1 + b_g1)
    hmma_gemm<E_GELU><<<dim3(12, NTOK / 128), 256>>>(
        qkvb + 384, 576, wtg1, 192, b_g1, nullptr, hb, 768, nullptr, nullptr);

    // 7) m = (h @ w_g2 + b_g2) * attn
    hmma_gemm<E_MUL><<<dim3(3, NTOK / 128), 256>>>(
        hb, 768, wtg2, 768, b_g2, nullptr, mb, 192, attn, nullptr);

    // 8) fused = m @ w_proj + b_proj  (fp32 + bf16)
    hmma_gemm<E_PROJ><<<dim3(3, NTOK / 128), 256>>>(
        mb, 192, wtp, 192, b_proj, fused, fusedb, 192, nullptr, nullptr);

    // 9) recon GEMM + fused L1 loss
    hmma_gemm<E_LOSS><<<dim3(3, NTOK / 128), 256>>>(
        fusedb, 192, wtr, 192, b_rec, nullptr, nullptr, 192, p, loss);

    // 10) window reverse + residual
    reverse_residual_kernel<<<NWIN, 256, TILE_SMEM>>>(fused, x, out);

    // 11) loss scalar
    if ((size_t)out_size > OUT_MAIN)
        finalize_loss_kernel<<<1, 1>>>(loss, out, (size_t)out_size - 1);
}

// round 6
// speedup vs baseline: 1.0771x; 1.0771x over previous
#include <cuda_runtime.h>
#include <cuda_bf16.h>
#include <math.h>
#include <stdint.h>

// ---------------- problem constants ----------------
#define CDIM   192
#define IMGHW  224
#define HW     (IMGHW*IMGHW)          // 50176
#define BATCH  4
#define HWC    ((size_t)CDIM*HW)
#define NWIN   3136
#define NTOK   200704                 // NWIN * 64 == BATCH*HW
#define NHEADS 6
#define OUT_MAIN ((size_t)BATCH*HWC)  // 38,535,168
#define RECON_DENOM 38535168.0

// ---------------- scratch (device globals) ----------------
__device__ __align__(16) float g_attn[(size_t)NTOK*192];
__device__ __align__(16) float g_f2  [(size_t)NTOK*192];   // NHWC dwconv out
__device__ __align__(16) float g_p   [(size_t)NTOK*192];   // fp32 p (loss ref)
__device__ __align__(16) __nv_bfloat16 g_pb   [(size_t)NTOK*192];  // xT first, then pb
__device__ __align__(16) __nv_bfloat16 g_qkvb [(size_t)NTOK*576];  // f1b first, then qkv
__device__ __align__(16) __nv_bfloat16 g_hb   [(size_t)NTOK*768];
__device__ __align__(16) __nv_bfloat16 g_wt_pre [192*192];
__device__ __align__(16) __nv_bfloat16 g_wt_qkv [576*192];
__device__ __align__(16) __nv_bfloat16 g_wt_g1  [768*192];
__device__ __align__(16) __nv_bfloat16 g_wt_g2  [192*768];
__device__ __align__(16) __nv_bfloat16 g_wt_proj[192*192];
__device__ __align__(16) __nv_bfloat16 g_wt_rec [192*192];
__device__ float g_loss[1];

// ---------------- HMMA m16n8k16 bf16 helper ----------------
__device__ __forceinline__ void mma_bf16(float c[4],
    uint32_t a0, uint32_t a1, uint32_t a2, uint32_t a3,
    uint32_t b0, uint32_t b1)
{
    asm volatile(
        "mma.sync.aligned.m16n8k16.row.col.f32.bf16.bf16.f32 "
        "{%0,%1,%2,%3}, {%4,%5,%6,%7}, {%8,%9}, {%0,%1,%2,%3};"
        : "+f"(c[0]), "+f"(c[1]), "+f"(c[2]), "+f"(c[3])
        : "r"(a0), "r"(a1), "r"(a2), "r"(a3), "r"(b0), "r"(b1));
}

// ---------------- standalone HMMA GEMM (conv1x1 / qkv / g1) ----------------
// C[M, Ntot] = A[M,K]bf16 @ BT[Ntot,K]bf16^T + fused epilogue.
// CTA tile 128 x 64, K-chunk 32, double buffered, 256 threads (8 warps 4x2).
enum { E_BIASN = 0, E_GELU = 1 };

template<int EPI>
__global__ void __launch_bounds__(256)
hmma_gemm(const __nv_bfloat16* __restrict__ A, int lda,
          const __nv_bfloat16* __restrict__ BT, int K,
          const float* __restrict__ bias,
          __nv_bfloat16* __restrict__ Cb, int ldc)
{
    __shared__ __align__(16) __nv_bfloat16 sA[2][128][40];
    __shared__ __align__(16) __nv_bfloat16 sB[2][64][40];

    const int tid = threadIdx.x;
    const int lane = tid & 31, wid = tid >> 5;
    const int wm = wid & 3, wn = wid >> 2;

    const __nv_bfloat16* Ab = A + (size_t)(blockIdx.y * 128) * lda;
    const __nv_bfloat16* Bb = BT + (size_t)(blockIdx.x * 64) * K;

    float acc[2][4][4] = {};
    const int nk = K >> 5;

    #define LOAD_CHUNK(buf, k0) do {                                          \
        _Pragma("unroll")                                                     \
        for (int it = 0; it < 2; it++) {                                      \
            int id = tid + it * 256;                                          \
            int r = id >> 2, q = id & 3;                                      \
            *(uint4*)&sA[buf][r][q * 8] =                                     \
                *(const uint4*)(Ab + (size_t)r * lda + (k0) + q * 8);         \
        }                                                                     \
        {                                                                     \
            int r = tid >> 2, q = tid & 3;                                    \
            *(uint4*)&sB[buf][r][q * 8] =                                     \
                *(const uint4*)(Bb + (size_t)r * K + (k0) + q * 8);           \
        }                                                                     \
    } while (0)

    LOAD_CHUNK(0, 0);
    __syncthreads();

    for (int kc = 0; kc < nk; kc++) {
        int b = kc & 1;
        if (kc + 1 < nk) { LOAD_CHUNK(b ^ 1, (kc + 1) * 32); }

        #pragma unroll
        for (int ks = 0; ks < 2; ks++) {
            const int kof = ks * 16 + (lane & 3) * 2;
            uint32_t af[2][4];
            #pragma unroll
            for (int mi = 0; mi < 2; mi++) {
                int r = wm * 32 + mi * 16 + (lane >> 2);
                af[mi][0] = *(const uint32_t*)&sA[b][r][kof];
                af[mi][1] = *(const uint32_t*)&sA[b][r + 8][kof];
                af[mi][2] = *(const uint32_t*)&sA[b][r][kof + 8];
                af[mi][3] = *(const uint32_t*)&sA[b][r + 8][kof + 8];
            }
            #pragma unroll
            for (int ni = 0; ni < 4; ni++) {
                int n = wn * 32 + ni * 8 + (lane >> 2);
                uint32_t b0 = *(const uint32_t*)&sB[b][n][kof];
                uint32_t b1 = *(const uint32_t*)&sB[b][n][kof + 8];
                #pragma unroll
                for (int mi = 0; mi < 2; mi++)
                    mma_bf16(acc[mi][ni], af[mi][0], af[mi][1], af[mi][2],
                             af[mi][3], b0, b1);
            }
        }
        __syncthreads();
    }
    #undef LOAD_CHUNK

    #pragma unroll
    for (int mi = 0; mi < 2; mi++) {
        #pragma unroll
        for (int ni = 0; ni < 4; ni++) {
            int r0 = blockIdx.y * 128 + wm * 32 + mi * 16 + (lane >> 2);
            int n0 = blockIdx.x * 64 + wn * 32 + ni * 8 + (lane & 3) * 2;
            float b0 = bias[n0], b1 = bias[n0 + 1];
            #pragma unroll
            for (int h = 0; h < 2; h++) {
                int r = r0 + h * 8;
                float v0 = acc[mi][ni][2 * h] + b0;
                float v1 = acc[mi][ni][2 * h + 1] + b1;
                if (EPI == E_GELU) {
                    v0 = 0.5f * v0 * (1.0f + erff(v0 * 0.70710678118654752f));
                    v1 = 0.5f * v1 * (1.0f + erff(v1 * 0.70710678118654752f));
                }
                __nv_bfloat162 h2 = __floats2bfloat162_rn(v0, v1);
                *(uint32_t*)(Cb + (size_t)r * ldc + n0) = *(uint32_t*)&h2;
            }
        }
    }
}

// ---------------- fused tail kernel ----------------
// One block per window (64 tokens). 256 threads, warps 2(M) x 4(N).
//   m     = (hb @ W_g2^T + b_g2) * attn        (K=768)
//   fused = m @ W_proj^T + b_proj              (K=192, A from smem)
//   rec   = fused @ W_rec^T + b_rec, loss += |rec - p|
//   out   = window_reverse(fused) + x          (NCHW)
// smem layout (bf16 elems): sA 2*64*40 | sB 2*192*40 | ms 64*200 | fs 64*200

__device__ __forceinline__ void tail_frag_mma(
    const __nv_bfloat16* __restrict__ Asrc, int asr, int akof,
    const __nv_bfloat16* __restrict__ Bsrc, int bkof,
    int wm, int wn, int lane, float acc[2][6][4])
{
    uint32_t af[2][4];
    #pragma unroll
    for (int mi = 0; mi < 2; mi++) {
        int r = wm * 32 + mi * 16 + (lane >> 2);
        const __nv_bfloat16* ap = Asrc + r * asr + akof;
        af[mi][0] = *(const uint32_t*)ap;
        af[mi][1] = *(const uint32_t*)(ap + 8 * asr);
        af[mi][2] = *(const uint32_t*)(ap + 8);
        af[mi][3] = *(const uint32_t*)(ap + 8 * asr + 8);
    }
    #pragma unroll
    for (int ni = 0; ni < 6; ni++) {
        int n = wn * 48 + ni * 8 + (lane >> 2);
        const __nv_bfloat16* bp = Bsrc + n * 40 + bkof;
        uint32_t b0 = *(const uint32_t*)bp;
        uint32_t b1 = *(const uint32_t*)(bp + 8);
        #pragma unroll
        for (int mi = 0; mi < 2; mi++)
            mma_bf16(acc[mi][ni], af[mi][0], af[mi][1], af[mi][2], af[mi][3],
                     b0, b1);
    }
}

#define TAIL_SMEM ((2*64*40 + 2*192*40 + 64*200 + 64*200) * 2)   // 92160 B

__global__ void __launch_bounds__(256)
tail_kernel(const __nv_bfloat16* __restrict__ hb,
            const __nv_bfloat16* __restrict__ wg2, const float* __restrict__ bg2,
            const float* __restrict__ attn,
            const __nv_bfloat16* __restrict__ wproj, const float* __restrict__ bproj,
            const __nv_bfloat16* __restrict__ wrec, const float* __restrict__ brec,
            const float* __restrict__ p, const float* __restrict__ xin,
            float* __restrict__ out, float* __restrict__ lossAcc)
{
    extern __shared__ __align__(16) __nv_bfloat16 sm[];
    __nv_bfloat16* sA = sm;                    // 2 * 2560
    __nv_bfloat16* sB = sm + 5120;             // 2 * 7680
    __nv_bfloat16* ms = sm + 5120 + 15360;     // 64 * 200
    __nv_bfloat16* fs = ms + 12800;            // 64 * 200
    __shared__ float red[256];

    const int tid = threadIdx.x;
    const int lane = tid & 31, wid = tid >> 5;
    const int wm = wid & 1, wn = wid >> 1;
    const int win = blockIdx.x;
    const __nv_bfloat16* Ab = hb + (size_t)win * 64 * 768;

    #define TK_LOADA(buf, k0) do {                                            \
        int r = tid >> 2, q = tid & 3;                                        \
        *(uint4*)(sA + (buf) * 2560 + r * 40 + q * 8) =                       \
            *(const uint4*)(Ab + (size_t)r * 768 + (k0) + q * 8);             \
    } while (0)
    #define TK_LOADB(buf, Bg, ldb, k0) do {                                   \
        _Pragma("unroll")                                                     \
        for (int i = 0; i < 3; i++) {                                         \
            int id = tid + i * 256;                                           \
            int r = id >> 2, q = id & 3;                                      \
            *(uint4*)(sB + (buf) * 7680 + r * 40 + q * 8) =                   \
                *(const uint4*)((Bg) + (size_t)r * (ldb) + (k0) + q * 8);     \
        }                                                                     \
    } while (0)

    // ---- stage 1: m = (hb @ W_g2^T + b_g2) * attn,  K = 768 ----
    float acc1[2][6][4] = {};
    TK_LOADA(0, 0);
    TK_LOADB(0, wg2, 768, 0);
    __syncthreads();
    for (int kc = 0; kc < 24; kc++) {
        int b = kc & 1;
        if (kc < 23) { TK_LOADA(b ^ 1, (kc + 1) * 32); TK_LOADB(b ^ 1, wg2, 768, (kc + 1) * 32); }
        #pragma unroll
        for (int ks = 0; ks < 2; ks++) {
            int kof = ks * 16 + (lane & 3) * 2;
            tail_frag_mma(sA + b * 2560, 40, kof, sB + b * 7680, kof,
                          wm, wn, lane, acc1);
        }
        __syncthreads();
    }
    // epilogue 1 -> ms (bf16)
    #pragma unroll
    for (int mi = 0; mi < 2; mi++) {
        #pragma unroll
        for (int ni = 0; ni < 6; ni++) {
            int col = wn * 48 + ni * 8 + (lane & 3) * 2;
            float b0 = bg2[col], b1 = bg2[col + 1];
            #pragma unroll
            for (int h = 0; h < 2; h++) {
                int row = wm * 32 + mi * 16 + (lane >> 2) + h * 8;
                size_t ci = ((size_t)win * 64 + row) * 192 + col;
                float v0 = (acc1[mi][ni][2 * h]     + b0) * attn[ci];
                float v1 = (acc1[mi][ni][2 * h + 1] + b1) * attn[ci + 1];
                __nv_bfloat162 h2 = __floats2bfloat162_rn(v0, v1);
                *(uint32_t*)(ms + row * 200 + col) = *(uint32_t*)&h2;
            }
        }
    }
    __syncthreads();

    // ---- stage 2: fused = ms @ W_proj^T + b_proj,  K = 192 ----
    float acc2[2][6][4] = {};
    TK_LOADB(0, wproj, 192, 0);
    __syncthreads();
    for (int kc = 0; kc < 6; kc++) {
        int b = kc & 1;
        if (kc < 5) TK_LOADB(b ^ 1, wproj, 192, (kc + 1) * 32);
        #pragma unroll
        for (int ks = 0; ks < 2; ks++) {
            int kof = ks * 16 + (lane & 3) * 2;
            tail_frag_mma(ms, 200, kc * 32 + kof, sB + b * 7680, kof,
                          wm, wn, lane, acc2);
        }
        __syncthreads();
    }
    // epilogue 2 -> fs (bf16)
    #pragma unroll
    for (int mi = 0; mi < 2; mi++) {
        #pragma unroll
        for (int ni = 0; ni < 6; ni++) {
            int col = wn * 48 + ni * 8 + (lane & 3) * 2;
            float b0 = bproj[col], b1 = bproj[col + 1];
            #pragma unroll
            for (int h = 0; h < 2; h++) {
                int row = wm * 32 + mi * 16 + (lane >> 2) + h * 8;
                float v0 = acc2[mi][ni][2 * h]     + b0;
                float v1 = acc2[mi][ni][2 * h + 1] + b1;
                __nv_bfloat162 h2 = __floats2bfloat162_rn(v0, v1);
                *(uint32_t*)(fs + row * 200 + col) = *(uint32_t*)&h2;
            }
        }
    }
    __syncthreads();

    // ---- stage 3: rec = fs @ W_rec^T + b_rec, L1 loss vs p ----
    float acc3[2][6][4] = {};
    TK_LOADB(0, wrec, 192, 0);
    __syncthreads();
    for (int kc = 0; kc < 6; kc++) {
        int b = kc & 1;
        if (kc < 5) TK_LOADB(b ^ 1, wrec, 192, (kc + 1) * 32);
        #pragma unroll
        for (int ks = 0; ks < 2; ks++) {
            int kof = ks * 16 + (lane & 3) * 2;
            tail_frag_mma(fs, 200, kc * 32 + kof, sB + b * 7680, kof,
                          wm, wn, lane, acc3);
        }
        __syncthreads();
    }
    float lsum = 0.f;
    #pragma unroll
    for (int mi = 0; mi < 2; mi++) {
        #pragma unroll
        for (int ni = 0; ni < 6; ni++) {
            int col = wn * 48 + ni * 8 + (lane & 3) * 2;
            float b0 = brec[col], b1 = brec[col + 1];
            #pragma unroll
            for (int h = 0; h < 2; h++) {
                int row = wm * 32 + mi * 16 + (lane >> 2) + h * 8;
                size_t ci = ((size_t)win * 64 + row) * 192 + col;
                lsum += fabsf(acc3[mi][ni][2 * h]     + b0 - p[ci]);
                lsum += fabsf(acc3[mi][ni][2 * h + 1] + b1 - p[ci + 1]);
            }
        }
    }
    red[tid] = lsum;
    __syncthreads();
    #pragma unroll
    for (int s = 128; s > 0; s >>= 1) {
        if (tid < s) red[tid] += red[tid + s];
        __syncthreads();
    }
    if (tid == 0) atomicAdd(lossAcc, red[0]);

    // ---- stage 4: window reverse + residual -> NCHW out ----
    int bb = win / 784;
    int wr = win % 784;
    int wy = wr / 28, wx = wr % 28;
    size_t base = (size_t)bb * HWC + (size_t)(wy * 8) * IMGHW + wx * 8;
    for (int idx = tid; idx < 64 * 192; idx += 256) {
        int c = idx >> 6, t = idx & 63;
        int iy = t >> 3, ix = t & 7;
        size_t o = base + (size_t)c * HW + iy * IMGHW + ix;
        out[o] = __bfloat162float(fs[t * 200 + c]) + xin[o];
    }
    #undef TK_LOADA
    #undef TK_LOADB
}

// ---------------- x transpose: NCHW fp32 -> NHWC bf16 ----------------
__global__ void __launch_bounds__(256)
transpose_x_kernel(const float* __restrict__ x, __nv_bfloat16* __restrict__ xt)
{
    __shared__ float tile[32][33];
    int s0 = blockIdx.x * 32, c0 = blockIdx.y * 32, b = blockIdx.z;
    int tx = threadIdx.x & 31, ty = threadIdx.x >> 5;
    const float* xp = x + (size_t)b * HWC;
    #pragma unroll
    for (int j = 0; j < 4; j++)
        tile[ty + 8 * j][tx] = xp[(size_t)(c0 + ty + 8 * j) * HW + s0 + tx];
    __syncthreads();
    __nv_bfloat16* op = xt + (size_t)b * HW * CDIM;
    #pragma unroll
    for (int j = 0; j < 4; j++)
        op[(size_t)(s0 + ty + 8 * j) * CDIM + c0 + tx] =
            __float2bfloat16(tile[tx][ty + 8 * j]);
}

// ---------------- depthwise 3x3, NHWC, bf16 in / fp32 out ----------------
__global__ void __launch_bounds__(192)
dwconv_nhwc_kernel(const __nv_bfloat16* __restrict__ in,
                   const float* __restrict__ w, const float* __restrict__ bias,
                   float* __restrict__ out)
{
    int c = threadIdx.x;
    int pix = blockIdx.x;
    int b = pix / HW, s = pix % HW;
    int y = s / IMGHW, xq = s % IMGHW;
    const __nv_bfloat16* ip = in + (size_t)b * HW * CDIM;
    float acc = bias[c];
    #pragma unroll
    for (int ky = 0; ky < 3; ky++) {
        int yy = y + ky - 1;
        if (yy < 0 || yy >= IMGHW) continue;
        #pragma unroll
        for (int kx = 0; kx < 3; kx++) {
            int xx = xq + kx - 1;
            if (xx < 0 || xx >= IMGHW) continue;
            acc = fmaf(__bfloat162float(ip[(size_t)(yy * IMGHW + xx) * CDIM + c]),
                       w[c * 9 + ky * 3 + kx], acc);
        }
    }
    out[(size_t)pix * CDIM + c] = acc;
}

// ---------------- LayerNorm + window partition ----------------
__global__ void __launch_bounds__(256)
ln_partition_kernel(const float* __restrict__ f2,
                    const float* __restrict__ lng, const float* __restrict__ lnb,
                    float* __restrict__ p, __nv_bfloat16* __restrict__ pb)
{
    extern __shared__ float tile[];    // [64][193]
    __shared__ float mu[64], rs[64];
    int win = blockIdx.x;
    int b  = win / 784;
    int wr = win % 784;
    int wy = wr / 28, wx = wr % 28;
    const float* fp = f2 + (size_t)b * HW * CDIM;

    for (int idx = threadIdx.x; idx < 64 * 192; idx += 256) {
        int t = idx / 192, c = idx % 192;
        int iy = t >> 3, ix = t & 7;
        tile[t * 193 + c] =
            fp[(size_t)((wy * 8 + iy) * IMGHW + wx * 8 + ix) * CDIM + c];
    }
    __syncthreads();
    if (threadIdx.x < 64) {
        int t = threadIdx.x;
        float s = 0.f, s2 = 0.f;
        for (int c = 0; c < 192; c++) {
            float v = tile[t * 193 + c];
            s += v; s2 = fmaf(v, v, s2);
        }
        float m = s * (1.0f / 192.0f);
        float var = s2 * (1.0f / 192.0f) - m * m;
        mu[t] = m;
        rs[t] = rsqrtf(var + 1e-6f);
    }
    __syncthreads();
    size_t pbase = (size_t)win * (64 * 192);
    for (int idx = threadIdx.x; idx < 64 * 192; idx += 256) {
        int t = idx / 192, c = idx % 192;
        float v = (tile[t * 193 + c] - mu[t]) * rs[t];
        v = fmaf(v, lng[c], lnb[c]);
        p[pbase + idx] = v;
        pb[pbase + idx] = __float2bfloat16(v);
    }
}

// ---------------- windowed multi-head attention ----------------
__global__ void __launch_bounds__(64)
attention_kernel(const __nv_bfloat16* __restrict__ qkv, float* __restrict__ outat)
{
    __shared__ float ks[64][33];
    __shared__ float vs[64][33];
    __shared__ float ps[64][65];
    int bid = blockIdx.x;
    int win = bid / NHEADS, h = bid % NHEADS;
    size_t qbase = (size_t)win * 64 * 576;
    int hc = h * 32;

    for (int idx = threadIdx.x; idx < 64 * 32; idx += 64) {
        int t = idx >> 5, c = idx & 31;
        ks[t][c] = __bfloat162float(qkv[qbase + (size_t)t * 576 + 192 + hc + c]);
        vs[t][c] = __bfloat162float(qkv[qbase + (size_t)t * 576 + 384 + hc + c]);
    }
    __syncthreads();

    int r = threadIdx.x;
    float q[32];
    const __nv_bfloat16* qp = &qkv[qbase + (size_t)r * 576 + hc];
    #pragma unroll
    for (int c = 0; c < 32; c++) q[c] = __bfloat162float(qp[c]);

    float mx = -1e30f;
    for (int t = 0; t < 64; t++) {
        float d = 0.f;
        #pragma unroll
        for (int c = 0; c < 32; c++) d = fmaf(q[c], ks[t][c], d);
        d *= 0.17677669529663687f;
        ps[r][t] = d;
        mx = fmaxf(mx, d);
    }
    float sum = 0.f;
    for (int t = 0; t < 64; t++) {
        float e = expf(ps[r][t] - mx);
        ps[r][t] = e;
        sum += e;
    }
    float inv = 1.0f / sum;
    float* op = &outat[((size_t)win * 64 + r) * 192 + hc];
    for (int c = 0; c < 32; c++) {
        float a = 0.f;
        for (int t = 0; t < 64; t++) a = fmaf(ps[r][t], vs[t][c], a);
        op[c] = a * inv;
    }
}

// ---------------- weight prep ----------------
__global__ void transpose_w_kernel(const float* __restrict__ w,
                                   __nv_bfloat16* __restrict__ wt, int K, int N)
{
    int i = blockIdx.x * 256 + threadIdx.x;
    if (i < K * N) {
        int k = i / N, n = i % N;
        wt[n * K + k] = __float2bfloat16(w[i]);
    }
}
__global__ void convert_w_kernel(const float* __restrict__ w,
                                 __nv_bfloat16* __restrict__ wt, int n)
{
    int i = blockIdx.x * 256 + threadIdx.x;
    if (i < n) wt[i] = __float2bfloat16(w[i]);
}

// ---------------- tiny helpers ----------------
__global__ void zero_loss_kernel(float* l) { *l = 0.f; }
__global__ void finalize_loss_kernel(const float* l, float* out, size_t pos)
{
    out[pos] = l[0] * (float)(0.1 / RECON_DENOM);
}

// ---------------- launch ----------------
extern "C" void kernel_launch(void* const* d_in, const int* in_sizes, int n_in,
                              void* d_out, int out_size)
{
    const float* x      = (const float*)d_in[0];
    const float* w_pre1 = (const float*)d_in[1];
    const float* b_pre1 = (const float*)d_in[2];
    const float* w_dw   = (const float*)d_in[3];
    const float* b_dw   = (const float*)d_in[4];
    const float* ln_g   = (const float*)d_in[5];
    const float* ln_b   = (const float*)d_in[6];
    const float* w_qkv  = (const float*)d_in[7];
    const float* b_qkv  = (const float*)d_in[8];
    const float* w_proj = (const float*)d_in[9];
    const float* b_proj = (const float*)d_in[10];
    const float* w_g1   = (const float*)d_in[11];
    const float* b_g1   = (const float*)d_in[12];
    const float* w_g2   = (const float*)d_in[13];
    const float* b_g2   = (const float*)d_in[14];
    const float* w_rec  = (const float*)d_in[15];
    const float* b_rec  = (const float*)d_in[16];
    float* out = (float*)d_out;

    float *attn, *f2, *p, *loss;
    __nv_bfloat16 *pb, *qkvb, *hb;
    __nv_bfloat16 *wtpre, *wtq, *wtg1, *wtg2, *wtp, *wtr;
    cudaGetSymbolAddress((void**)&attn,  g_attn);
    cudaGetSymbolAddress((void**)&f2,    g_f2);
    cudaGetSymbolAddress((void**)&p,     g_p);
    cudaGetSymbolAddress((void**)&pb,    g_pb);
    cudaGetSymbolAddress((void**)&qkvb,  g_qkvb);
    cudaGetSymbolAddress((void**)&hb,    g_hb);
    cudaGetSymbolAddress((void**)&wtpre, g_wt_pre);
    cudaGetSymbolAddress((void**)&wtq,   g_wt_qkv);
    cudaGetSymbolAddress((void**)&wtg1,  g_wt_g1);
    cudaGetSymbolAddress((void**)&wtg2,  g_wt_g2);
    cudaGetSymbolAddress((void**)&wtp,   g_wt_proj);
    cudaGetSymbolAddress((void**)&wtr,   g_wt_rec);
    cudaGetSymbolAddress((void**)&loss,  g_loss);

    __nv_bfloat16* xt  = pb;     // xT dead before pb is written (by LN)
    __nv_bfloat16* f1b = qkvb;   // f1b dead before qkv GEMM writes

    const int TILE_SMEM = 64 * 193 * 4;
    cudaFuncSetAttribute(ln_partition_kernel,
                         cudaFuncAttributeMaxDynamicSharedMemorySize, TILE_SMEM);
    cudaFuncSetAttribute(tail_kernel,
                         cudaFuncAttributeMaxDynamicSharedMemorySize, TAIL_SMEM);

    zero_loss_kernel<<<1, 1>>>(loss);

    // weight prep (tiny)
    convert_w_kernel<<<(192*192 + 255) / 256, 256>>>(w_pre1, wtpre, 192*192);
    transpose_w_kernel<<<(192*576 + 255) / 256, 256>>>(w_qkv, wtq, 192, 576);
    transpose_w_kernel<<<(192*768 + 255) / 256, 256>>>(w_g1, wtg1, 192, 768);
    transpose_w_kernel<<<(768*192 + 255) / 256, 256>>>(w_g2, wtg2, 768, 192);
    transpose_w_kernel<<<(192*192 + 255) / 256, 256>>>(w_proj, wtp, 192, 192);
    transpose_w_kernel<<<(192*192 + 255) / 256, 256>>>(w_rec, wtr, 192, 192);

    // 0) x -> NHWC bf16
    transpose_x_kernel<<<dim3(HW / 32, CDIM / 32, BATCH), 256>>>(x, xt);

    // 1) 1x1 conv as HMMA GEMM
    hmma_gemm<E_BIASN><<<dim3(3, NTOK / 128), 256>>>(
        xt, 192, wtpre, 192, b_pre1, f1b, 192);

    // 2) depthwise 3x3 (NHWC)
    dwconv_nhwc_kernel<<<NTOK, 192>>>(f1b, w_dw, b_dw, f2);

    // 3) LN + window partition -> p (fp32 + bf16)
    ln_partition_kernel<<<NWIN, 256, TILE_SMEM>>>(f2, ln_g, ln_b, p, pb);

    // 4) qkv = p @ w_qkv + b
    hmma_gemm<E_BIASN><<<dim3(9, NTOK / 128), 256>>>(
        pb, 192, wtq, 192, b_qkv, qkvb, 576);

    // 5) windowed attention -> attn fp32
    attention_kernel<<<NWIN * NHEADS, 64>>>(qkvb, attn);

    // 6) h = gelu(v @ w_g1 + b_g1)
    hmma_gemm<E_GELU><<<dim3(12, NTOK / 128), 256>>>(
        qkvb + 384, 576, wtg1, 192, b_g1, hb, 768);

    // 7-10) fused tail: g2 GEMM + gate + proj + rec/loss + reverse/residual
    tail_kernel<<<NWIN, 256, TAIL_SMEM>>>(
        hb, wtg2, b_g2, attn, wtp, b_proj, wtr, b_rec, p, x, out, loss);

    // 11) loss scalar
    if ((size_t)out_size > OUT_MAIN)
        finalize_loss_kernel<<<1, 1>>>(loss, out, (size_t)out_size - 1);
}

// round 7
// speedup vs baseline: 1.5479x; 1.4372x over previous
#include <cuda_runtime.h>
#include <cuda_bf16.h>
#include <math.h>
#include <stdint.h>

// ---------------- problem constants ----------------
#define CDIM   192
#define IMGHW  224
#define HW     (IMGHW*IMGHW)          // 50176
#define BATCH  4
#define HWC    ((size_t)CDIM*HW)
#define NWIN   3136
#define NTOK   200704                 // NWIN * 64 == BATCH*HW
#define NHEADS 6
#define OUT_MAIN ((size_t)BATCH*HWC)  // 38,535,168
#define RECON_DENOM 38535168.0

// ---------------- scratch (device globals) ----------------
__device__ __align__(16) __nv_bfloat16 g_attnb[(size_t)NTOK*192];
__device__ __align__(16) __nv_bfloat16 g_pb   [(size_t)NTOK*192];  // xT first, then pb
__device__ __align__(16) __nv_bfloat16 g_qkvb [(size_t)NTOK*576];  // f1b first, then qkv
__device__ __align__(16) __nv_bfloat16 g_hb   [(size_t)NTOK*768];
__device__ __align__(16) __nv_bfloat16 g_wt_pre [192*192];
__device__ __align__(16) __nv_bfloat16 g_wt_qkv [576*192];
__device__ __align__(16) __nv_bfloat16 g_wt_g1  [768*192];
__device__ __align__(16) __nv_bfloat16 g_wt_g2  [192*768];
__device__ __align__(16) __nv_bfloat16 g_wt_proj[192*192];
__device__ __align__(16) __nv_bfloat16 g_wt_rec [192*192];
__device__ float g_loss[1];

// ---------------- HMMA m16n8k16 bf16 helper ----------------
__device__ __forceinline__ void mma_bf16(float c[4],
    uint32_t a0, uint32_t a1, uint32_t a2, uint32_t a3,
    uint32_t b0, uint32_t b1)
{
    asm volatile(
        "mma.sync.aligned.m16n8k16.row.col.f32.bf16.bf16.f32 "
        "{%0,%1,%2,%3}, {%4,%5,%6,%7}, {%8,%9}, {%0,%1,%2,%3};"
        : "+f"(c[0]), "+f"(c[1]), "+f"(c[2]), "+f"(c[3])
        : "r"(a0), "r"(a1), "r"(a2), "r"(a3), "r"(b0), "r"(b1));
}

// ---------------- standalone HMMA GEMM (conv1x1 / qkv / g1) ----------------
// C[M, Ntot] = A[M,K]bf16 @ BT[Ntot,K]bf16^T + epilogue.
// CTA tile 128 x 96, K-chunk 32, double buffered, 256 threads (8 warps 4Mx2N).
enum { E_BIASN = 0, E_GELU = 1 };

template<int EPI>
__global__ void __launch_bounds__(256)
hmma_gemm(const __nv_bfloat16* __restrict__ A, int lda,
          const __nv_bfloat16* __restrict__ BT, int K,
          const float* __restrict__ bias,
          __nv_bfloat16* __restrict__ Cb, int ldc)
{
    __shared__ __align__(16) __nv_bfloat16 sA[2][128][40];
    __shared__ __align__(16) __nv_bfloat16 sB[2][96][40];

    const int tid = threadIdx.x;
    const int lane = tid & 31, wid = tid >> 5;
    const int wm = wid & 3, wn = wid >> 2;

    const __nv_bfloat16* Ab = A + (size_t)(blockIdx.y * 128) * lda;
    const __nv_bfloat16* Bb = BT + (size_t)(blockIdx.x * 96) * K;

    float acc[2][6][4] = {};
    const int nk = K >> 5;

    #define LOAD_CHUNK(buf, k0) do {                                          \
        _Pragma("unroll")                                                     \
        for (int it = 0; it < 2; it++) {                                      \
            int id = tid + it * 256;                                          \
            int r = id >> 2, q = id & 3;                                      \
            *(uint4*)&sA[buf][r][q * 8] =                                     \
                *(const uint4*)(Ab + (size_t)r * lda + (k0) + q * 8);         \
        }                                                                     \
        _Pragma("unroll")                                                     \
        for (int it = 0; it < 2; it++) {                                      \
            int id = tid + it * 256;                                          \
            if (id < 384) {                                                   \
                int r = id >> 2, q = id & 3;                                  \
                *(uint4*)&sB[buf][r][q * 8] =                                 \
                    *(const uint4*)(Bb + (size_t)r * K + (k0) + q * 8);       \
            }                                                                 \
        }                                                                     \
    } while (0)

    LOAD_CHUNK(0, 0);
    __syncthreads();

    for (int kc = 0; kc < nk; kc++) {
        int b = kc & 1;
        if (kc + 1 < nk) { LOAD_CHUNK(b ^ 1, (kc + 1) * 32); }

        #pragma unroll
        for (int ks = 0; ks < 2; ks++) {
            const int kof = ks * 16 + (lane & 3) * 2;
            uint32_t af[2][4];
            #pragma unroll
            for (int mi = 0; mi < 2; mi++) {
                int r = wm * 32 + mi * 16 + (lane >> 2);
                af[mi][0] = *(const uint32_t*)&sA[b][r][kof];
                af[mi][1] = *(const uint32_t*)&sA[b][r + 8][kof];
                af[mi][2] = *(const uint32_t*)&sA[b][r][kof + 8];
                af[mi][3] = *(const uint32_t*)&sA[b][r + 8][kof + 8];
            }
            #pragma unroll
            for (int ni = 0; ni < 6; ni++) {
                int n = wn * 48 + ni * 8 + (lane >> 2);
                uint32_t b0 = *(const uint32_t*)&sB[b][n][kof];
                uint32_t b1 = *(const uint32_t*)&sB[b][n][kof + 8];
                #pragma unroll
                for (int mi = 0; mi < 2; mi++)
                    mma_bf16(acc[mi][ni], af[mi][0], af[mi][1], af[mi][2],
                             af[mi][3], b0, b1);
            }
        }
        __syncthreads();
    }
    #undef LOAD_CHUNK

    #pragma unroll
    for (int mi = 0; mi < 2; mi++) {
        #pragma unroll
        for (int ni = 0; ni < 6; ni++) {
            int r0 = blockIdx.y * 128 + wm * 32 + mi * 16 + (lane >> 2);
            int n0 = blockIdx.x * 96 + wn * 48 + ni * 8 + (lane & 3) * 2;
            float b0 = bias[n0], b1 = bias[n0 + 1];
            #pragma unroll
            for (int h = 0; h < 2; h++) {
                int r = r0 + h * 8;
                float v0 = acc[mi][ni][2 * h] + b0;
                float v1 = acc[mi][ni][2 * h + 1] + b1;
                if (EPI == E_GELU) {
                    v0 = 0.5f * v0 * (1.0f + erff(v0 * 0.70710678118654752f));
                    v1 = 0.5f * v1 * (1.0f + erff(v1 * 0.70710678118654752f));
                }
                __nv_bfloat162 h2 = __floats2bfloat162_rn(v0, v1);
                *(uint32_t*)(Cb + (size_t)r * ldc + n0) = *(uint32_t*)&h2;
            }
        }
    }
}

// ---------------- fused tail kernel ----------------
// One block per window (64 tokens). 256 threads, warps 2(M) x 4(N).
__device__ __forceinline__ void tail_frag_mma(
    const __nv_bfloat16* __restrict__ Asrc, int asr, int akof,
    const __nv_bfloat16* __restrict__ Bsrc, int bkof,
    int wm, int wn, int lane, float acc[2][6][4])
{
    uint32_t af[2][4];
    #pragma unroll
    for (int mi = 0; mi < 2; mi++) {
        int r = wm * 32 + mi * 16 + (lane >> 2);
        const __nv_bfloat16* ap = Asrc + r * asr + akof;
        af[mi][0] = *(const uint32_t*)ap;
        af[mi][1] = *(const uint32_t*)(ap + 8 * asr);
        af[mi][2] = *(const uint32_t*)(ap + 8);
        af[mi][3] = *(const uint32_t*)(ap + 8 * asr + 8);
    }
    #pragma unroll
    for (int ni = 0; ni < 6; ni++) {
        int n = wn * 48 + ni * 8 + (lane >> 2);
        const __nv_bfloat16* bp = Bsrc + n * 40 + bkof;
        uint32_t b0 = *(const uint32_t*)bp;
        uint32_t b1 = *(const uint32_t*)(bp + 8);
        #pragma unroll
        for (int mi = 0; mi < 2; mi++)
            mma_bf16(acc[mi][ni], af[mi][0], af[mi][1], af[mi][2], af[mi][3],
                     b0, b1);
    }
}

#define TAIL_SMEM ((2*64*40 + 2*192*40 + 64*200 + 64*200) * 2)   // 92160 B

__global__ void __launch_bounds__(256)
tail_kernel(const __nv_bfloat16* __restrict__ hb,
            const __nv_bfloat16* __restrict__ wg2, const float* __restrict__ bg2,
            const __nv_bfloat16* __restrict__ attnb,
            const __nv_bfloat16* __restrict__ wproj, const float* __restrict__ bproj,
            const __nv_bfloat16* __restrict__ wrec, const float* __restrict__ brec,
            const __nv_bfloat16* __restrict__ pb, const float* __restrict__ xin,
            float* __restrict__ out, float* __restrict__ lossAcc)
{
    extern __shared__ __align__(16) __nv_bfloat16 sm[];
    __nv_bfloat16* sA = sm;                    // 2 * 2560
    __nv_bfloat16* sB = sm + 5120;             // 2 * 7680
    __nv_bfloat16* ms = sm + 5120 + 15360;     // 64 * 200
    __nv_bfloat16* fs = ms + 12800;            // 64 * 200
    __shared__ float red[256];

    const int tid = threadIdx.x;
    const int lane = tid & 31, wid = tid >> 5;
    const int wm = wid & 1, wn = wid >> 1;
    const int win = blockIdx.x;
    const __nv_bfloat16* Ab = hb + (size_t)win * 64 * 768;

    #define TK_LOADA(buf, k0) do {                                            \
        int r = tid >> 2, q = tid & 3;                                        \
        *(uint4*)(sA + (buf) * 2560 + r * 40 + q * 8) =                       \
            *(const uint4*)(Ab + (size_t)r * 768 + (k0) + q * 8);             \
    } while (0)
    #define TK_LOADB(buf, Bg, ldb, k0) do {                                   \
        _Pragma("unroll")                                                     \
        for (int i = 0; i < 3; i++) {                                         \
            int id = tid + i * 256;                                           \
            int r = id >> 2, q = id & 3;                                      \
            *(uint4*)(sB + (buf) * 7680 + r * 40 + q * 8) =                   \
                *(const uint4*)((Bg) + (size_t)r * (ldb) + (k0) + q * 8);     \
        }                                                                     \
    } while (0)

    // ---- stage 1: m = (hb @ W_g2^T + b_g2) * attn,  K = 768 ----
    float acc1[2][6][4] = {};
    TK_LOADA(0, 0);
    TK_LOADB(0, wg2, 768, 0);
    __syncthreads();
    for (int kc = 0; kc < 24; kc++) {
        int b = kc & 1;
        if (kc < 23) { TK_LOADA(b ^ 1, (kc + 1) * 32); TK_LOADB(b ^ 1, wg2, 768, (kc + 1) * 32); }
        #pragma unroll
        for (int ks = 0; ks < 2; ks++) {
            int kof = ks * 16 + (lane & 3) * 2;
            tail_frag_mma(sA + b * 2560, 40, kof, sB + b * 7680, kof,
                          wm, wn, lane, acc1);
        }
        __syncthreads();
    }
    #pragma unroll
    for (int mi = 0; mi < 2; mi++) {
        #pragma unroll
        for (int ni = 0; ni < 6; ni++) {
            int col = wn * 48 + ni * 8 + (lane & 3) * 2;
            float b0 = bg2[col], b1 = bg2[col + 1];
            #pragma unroll
            for (int h = 0; h < 2; h++) {
                int row = wm * 32 + mi * 16 + (lane >> 2) + h * 8;
                size_t ci = ((size_t)win * 64 + row) * 192 + col;
                __nv_bfloat162 av = *(const __nv_bfloat162*)(attnb + ci);
                float v0 = (acc1[mi][ni][2 * h]     + b0) * __bfloat162float(av.x);
                float v1 = (acc1[mi][ni][2 * h + 1] + b1) * __bfloat162float(av.y);
                __nv_bfloat162 h2 = __floats2bfloat162_rn(v0, v1);
                *(uint32_t*)(ms + row * 200 + col) = *(uint32_t*)&h2;
            }
        }
    }
    __syncthreads();

    // ---- stage 2: fused = ms @ W_proj^T + b_proj,  K = 192 ----
    float acc2[2][6][4] = {};
    TK_LOADB(0, wproj, 192, 0);
    __syncthreads();
    for (int kc = 0; kc < 6; kc++) {
        int b = kc & 1;
        if (kc < 5) TK_LOADB(b ^ 1, wproj, 192, (kc + 1) * 32);
        #pragma unroll
        for (int ks = 0; ks < 2; ks++) {
            int kof = ks * 16 + (lane & 3) * 2;
            tail_frag_mma(ms, 200, kc * 32 + kof, sB + b * 7680, kof,
                          wm, wn, lane, acc2);
        }
        __syncthreads();
    }
    #pragma unroll
    for (int mi = 0; mi < 2; mi++) {
        #pragma unroll
        for (int ni = 0; ni < 6; ni++) {
            int col = wn * 48 + ni * 8 + (lane & 3) * 2;
            float b0 = bproj[col], b1 = bproj[col + 1];
            #pragma unroll
            for (int h = 0; h < 2; h++) {
                int row = wm * 32 + mi * 16 + (lane >> 2) + h * 8;
                float v0 = acc2[mi][ni][2 * h]     + b0;
                float v1 = acc2[mi][ni][2 * h + 1] + b1;
                __nv_bfloat162 h2 = __floats2bfloat162_rn(v0, v1);
                *(uint32_t*)(fs + row * 200 + col) = *(uint32_t*)&h2;
            }
        }
    }
    __syncthreads();

    // ---- stage 3: rec = fs @ W_rec^T + b_rec, L1 loss vs pb ----
    float acc3[2][6][4] = {};
    TK_LOADB(0, wrec, 192, 0);
    __syncthreads();
    for (int kc = 0; kc < 6; kc++) {
        int b = kc & 1;
        if (kc < 5) TK_LOADB(b ^ 1, wrec, 192, (kc + 1) * 32);
        #pragma unroll
        for (int ks = 0; ks < 2; ks++) {
            int kof = ks * 16 + (lane & 3) * 2;
            tail_frag_mma(fs, 200, kc * 32 + kof, sB + b * 7680, kof,
                          wm, wn, lane, acc3);
        }
        __syncthreads();
    }
    float lsum = 0.f;
    #pragma unroll
    for (int mi = 0; mi < 2; mi++) {
        #pragma unroll
        for (int ni = 0; ni < 6; ni++) {
            int col = wn * 48 + ni * 8 + (lane & 3) * 2;
            float b0 = brec[col], b1 = brec[col + 1];
            #pragma unroll
            for (int h = 0; h < 2; h++) {
                int row = wm * 32 + mi * 16 + (lane >> 2) + h * 8;
                size_t ci = ((size_t)win * 64 + row) * 192 + col;
                __nv_bfloat162 pv = *(const __nv_bfloat162*)(pb + ci);
                lsum += fabsf(acc3[mi][ni][2 * h]     + b0 - __bfloat162float(pv.x));
                lsum += fabsf(acc3[mi][ni][2 * h + 1] + b1 - __bfloat162float(pv.y));
            }
        }
    }
    red[tid] = lsum;
    __syncthreads();
    #pragma unroll
    for (int s = 128; s > 0; s >>= 1) {
        if (tid < s) red[tid] += red[tid + s];
        __syncthreads();
    }
    if (tid == 0) atomicAdd(lossAcc, red[0]);

    // ---- stage 4: window reverse + residual -> NCHW out ----
    int bb = win / 784;
    int wr = win % 784;
    int wy = wr / 28, wx = wr % 28;
    size_t base = (size_t)bb * HWC + (size_t)(wy * 8) * IMGHW + wx * 8;
    for (int idx = tid; idx < 64 * 192; idx += 256) {
        int c = idx >> 6, t = idx & 63;
        int iy = t >> 3, ix = t & 7;
        size_t o = base + (size_t)c * HW + iy * IMGHW + ix;
        out[o] = __bfloat162float(fs[t * 200 + c]) + xin[o];
    }
    #undef TK_LOADA
    #undef TK_LOADB
}

// ---------------- x transpose: NCHW fp32 -> NHWC bf16 ----------------
__global__ void __launch_bounds__(256)
transpose_x_kernel(const float* __restrict__ x, __nv_bfloat16* __restrict__ xt)
{
    __shared__ float tile[32][33];
    int s0 = blockIdx.x * 32, c0 = blockIdx.y * 32, b = blockIdx.z;
    int tx = threadIdx.x & 31, ty = threadIdx.x >> 5;
    const float* xp = x + (size_t)b * HWC;
    #pragma unroll
    for (int j = 0; j < 4; j++)
        tile[ty + 8 * j][tx] = xp[(size_t)(c0 + ty + 8 * j) * HW + s0 + tx];
    __syncthreads();
    __nv_bfloat16* op = xt + (size_t)b * HW * CDIM;
    #pragma unroll
    for (int j = 0; j < 4; j++)
        op[(size_t)(s0 + ty + 8 * j) * CDIM + c0 + tx] =
            __float2bfloat16(tile[tx][ty + 8 * j]);
}

// ---------------- fused depthwise 3x3 + LayerNorm + window partition -----
// One block per pixel, 192 threads (one per channel). Writes pb (bf16).
__global__ void __launch_bounds__(192)
dwconv_ln_kernel(const __nv_bfloat16* __restrict__ in,
                 const float* __restrict__ w, const float* __restrict__ bias,
                 const float* __restrict__ lng, const float* __restrict__ lnb,
                 __nv_bfloat16* __restrict__ pb)
{
    __shared__ float warp_s[6], warp_s2[6];
    int c = threadIdx.x;
    int pix = blockIdx.x;
    int b = pix / HW, s = pix % HW;
    int y = s / IMGHW, xq = s % IMGHW;
    const __nv_bfloat16* ip = in + (size_t)b * HW * CDIM;
    float acc = bias[c];
    #pragma unroll
    for (int ky = 0; ky < 3; ky++) {
        int yy = y + ky - 1;
        if (yy < 0 || yy >= IMGHW) continue;
        #pragma unroll
        for (int kx = 0; kx < 3; kx++) {
            int xx = xq + kx - 1;
            if (xx < 0 || xx >= IMGHW) continue;
            acc = fmaf(__bfloat162float(ip[(size_t)(yy * IMGHW + xx) * CDIM + c]),
                       w[c * 9 + ky * 3 + kx], acc);
        }
    }
    // LN over 192 channels
    float s1 = acc, s2 = acc * acc;
    #pragma unroll
    for (int o = 16; o > 0; o >>= 1) {
        s1 += __shfl_xor_sync(0xFFFFFFFFu, s1, o);
        s2 += __shfl_xor_sync(0xFFFFFFFFu, s2, o);
    }
    if ((c & 31) == 0) { warp_s[c >> 5] = s1; warp_s2[c >> 5] = s2; }
    __syncthreads();
    float ts = 0.f, ts2 = 0.f;
    #pragma unroll
    for (int i = 0; i < 6; i++) { ts += warp_s[i]; ts2 += warp_s2[i]; }
    float mu = ts * (1.0f / 192.0f);
    float var = ts2 * (1.0f / 192.0f) - mu * mu;
    float v = (acc - mu) * rsqrtf(var + 1e-6f);
    v = fmaf(v, lng[c], lnb[c]);
    int win = b * 784 + (y >> 3) * 28 + (xq >> 3);
    int t = (y & 7) * 8 + (xq & 7);
    pb[((size_t)win * 64 + t) * 192 + c] = __float2bfloat16(v);
}

// ---------------- HMMA windowed attention ----------------
// One block per window, 768 threads = 24 warps (6 heads x 4 q-slices of 16).
#define ATT_SMEM ((64*584 + 192*72) * 2)   // 102400 B

__global__ void __launch_bounds__(768)
attention_kernel(const __nv_bfloat16* __restrict__ qkv,
                 __nv_bfloat16* __restrict__ attnb)
{
    extern __shared__ __align__(16) __nv_bfloat16 sq[];   // [64][584]
    __nv_bfloat16* vt = sq + 64 * 584;                    // [192][72]
    const int tid = threadIdx.x, lane = tid & 31, wid = tid >> 5;
    const int win = blockIdx.x;
    const __nv_bfloat16* src = qkv + (size_t)win * 64 * 576;

    #pragma unroll
    for (int i = 0; i < 6; i++) {
        int id = tid + i * 768;
        int row = id / 72, q = id % 72;
        *(uint4*)(sq + row * 584 + q * 8) =
            *(const uint4*)(src + (size_t)row * 576 + q * 8);
    }
    __syncthreads();
    #pragma unroll
    for (int i = 0; i < 16; i++) {
        int id = tid + i * 768;
        int t = id & 63, ch = id >> 6;
        vt[ch * 72 + t] = sq[t * 584 + 384 + ch];
    }
    __syncthreads();

    const int h = wid >> 2, q0 = (wid & 3) * 16;
    const int hc = h * 32;

    // scores: 16 rows x 64 cols
    float sc[8][4] = {};
    #pragma unroll
    for (int ks = 0; ks < 2; ks++) {
        int kof = ks * 16 + (lane & 3) * 2;
        const __nv_bfloat16* qp = sq + (q0 + (lane >> 2)) * 584 + hc + kof;
        uint32_t a0 = *(const uint32_t*)qp;
        uint32_t a1 = *(const uint32_t*)(qp + 8 * 584);
        uint32_t a2 = *(const uint32_t*)(qp + 8);
        uint32_t a3 = *(const uint32_t*)(qp + 8 * 584 + 8);
        #pragma unroll
        for (int nt = 0; nt < 8; nt++) {
            const __nv_bfloat16* kp =
                sq + (nt * 8 + (lane >> 2)) * 584 + 192 + hc + kof;
            mma_bf16(sc[nt], a0, a1, a2, a3,
                     *(const uint32_t*)kp, *(const uint32_t*)(kp + 8));
        }
    }

    // softmax (rows: lane>>2 and +8)
    float mlo = -1e30f, mhi = -1e30f;
    #pragma unroll
    for (int nt = 0; nt < 8; nt++) {
        #pragma unroll
        for (int j = 0; j < 4; j++) sc[nt][j] *= 0.17677669529663687f;
        mlo = fmaxf(mlo, fmaxf(sc[nt][0], sc[nt][1]));
        mhi = fmaxf(mhi, fmaxf(sc[nt][2], sc[nt][3]));
    }
    mlo = fmaxf(mlo, __shfl_xor_sync(0xFFFFFFFFu, mlo, 1));
    mlo = fmaxf(mlo, __shfl_xor_sync(0xFFFFFFFFu, mlo, 2));
    mhi = fmaxf(mhi, __shfl_xor_sync(0xFFFFFFFFu, mhi, 1));
    mhi = fmaxf(mhi, __shfl_xor_sync(0xFFFFFFFFu, mhi, 2));
    float slo = 0.f, shi = 0.f;
    #pragma unroll
    for (int nt = 0; nt < 8; nt++) {
        sc[nt][0] = __expf(sc[nt][0] - mlo);
        sc[nt][1] = __expf(sc[nt][1] - mlo);
        sc[nt][2] = __expf(sc[nt][2] - mhi);
        sc[nt][3] = __expf(sc[nt][3] - mhi);
        slo += sc[nt][0] + sc[nt][1];
        shi += sc[nt][2] + sc[nt][3];
    }
    slo += __shfl_xor_sync(0xFFFFFFFFu, slo, 1);
    slo += __shfl_xor_sync(0xFFFFFFFFu, slo, 2);
    shi += __shfl_xor_sync(0xFFFFFFFFu, shi, 1);
    shi += __shfl_xor_sync(0xFFFFFFFFu, shi, 2);
    float ilo = 1.0f / slo, ihi = 1.0f / shi;

    // P @ V  (P from score regs, V^T from smem)
    float o[4][4] = {};
    #pragma unroll
    for (int ks = 0; ks < 4; ks++) {
        __nv_bfloat162 p0 = __floats2bfloat162_rn(sc[2*ks][0],   sc[2*ks][1]);
        __nv_bfloat162 p1 = __floats2bfloat162_rn(sc[2*ks][2],   sc[2*ks][3]);
        __nv_bfloat162 p2 = __floats2bfloat162_rn(sc[2*ks+1][0], sc[2*ks+1][1]);
        __nv_bfloat162 p3 = __floats2bfloat162_rn(sc[2*ks+1][2], sc[2*ks+1][3]);
        int kof = ks * 16 + (lane & 3) * 2;
        #pragma unroll
        for (int nt = 0; nt < 4; nt++) {
            const __nv_bfloat16* vp = vt + (hc + nt * 8 + (lane >> 2)) * 72 + kof;
            mma_bf16(o[nt], *(uint32_t*)&p0, *(uint32_t*)&p1,
                     *(uint32_t*)&p2, *(uint32_t*)&p3,
                     *(const uint32_t*)vp, *(const uint32_t*)(vp + 8));
        }
    }

    int rlo = q0 + (lane >> 2), col = (lane & 3) * 2;
    #pragma unroll
    for (int nt = 0; nt < 4; nt++) {
        size_t ci = ((size_t)win * 64 + rlo) * 192 + hc + nt * 8 + col;
        __nv_bfloat162 w0 = __floats2bfloat162_rn(o[nt][0] * ilo, o[nt][1] * ilo);
        *(uint32_t*)(attnb + ci) = *(uint32_t*)&w0;
        __nv_bfloat162 w1 = __floats2bfloat162_rn(o[nt][2] * ihi, o[nt][3] * ihi);
        *(uint32_t*)(attnb + ci + (size_t)8 * 192) = *(uint32_t*)&w1;
    }
}

// ---------------- weight prep ----------------
__global__ void transpose_w_kernel(const float* __restrict__ w,
                                   __nv_bfloat16* __restrict__ wt, int K, int N)
{
    int i = blockIdx.x * 256 + threadIdx.x;
    if (i < K * N) {
        int k = i / N, n = i % N;
        wt[n * K + k] = __float2bfloat16(w[i]);
    }
}
__global__ void convert_w_kernel(const float* __restrict__ w,
                                 __nv_bfloat16* __restrict__ wt, int n)
{
    int i = blockIdx.x * 256 + threadIdx.x;
    if (i < n) wt[i] = __float2bfloat16(w[i]);
}

// ---------------- tiny helpers ----------------
__global__ void zero_loss_kernel(float* l) { *l = 0.f; }
__global__ void finalize_loss_kernel(const float* l, float* out, size_t pos)
{
    out[pos] = l[0] * (float)(0.1 / RECON_DENOM);
}

// ---------------- launch ----------------
extern "C" void kernel_launch(void* const* d_in, const int* in_sizes, int n_in,
                              void* d_out, int out_size)
{
    const float* x      = (const float*)d_in[0];
    const float* w_pre1 = (const float*)d_in[1];
    const float* b_pre1 = (const float*)d_in[2];
    const float* w_dw   = (const float*)d_in[3];
    const float* b_dw   = (const float*)d_in[4];
    const float* ln_g   = (const float*)d_in[5];
    const float* ln_b   = (const float*)d_in[6];
    const float* w_qkv  = (const float*)d_in[7];
    const float* b_qkv  = (const float*)d_in[8];
    const float* w_proj = (const float*)d_in[9];
    const float* b_proj = (const float*)d_in[10];
    const float* w_g1   = (const float*)d_in[11];
    const float* b_g1   = (const float*)d_in[12];
    const float* w_g2   = (const float*)d_in[13];
    const float* b_g2   = (const float*)d_in[14];
    const float* w_rec  = (const float*)d_in[15];
    const float* b_rec  = (const float*)d_in[16];
    float* out = (float*)d_out;

    float* loss;
    __nv_bfloat16 *attnb, *pb, *qkvb, *hb;
    __nv_bfloat16 *wtpre, *wtq, *wtg1, *wtg2, *wtp, *wtr;
    cudaGetSymbolAddress((void**)&attnb, g_attnb);
    cudaGetSymbolAddress((void**)&pb,    g_pb);
    cudaGetSymbolAddress((void**)&qkvb,  g_qkvb);
    cudaGetSymbolAddress((void**)&hb,    g_hb);
    cudaGetSymbolAddress((void**)&wtpre, g_wt_pre);
    cudaGetSymbolAddress((void**)&wtq,   g_wt_qkv);
    cudaGetSymbolAddress((void**)&wtg1,  g_wt_g1);
    cudaGetSymbolAddress((void**)&wtg2,  g_wt_g2);
    cudaGetSymbolAddress((void**)&wtp,   g_wt_proj);
    cudaGetSymbolAddress((void**)&wtr,   g_wt_rec);
    cudaGetSymbolAddress((void**)&loss,  g_loss);

    __nv_bfloat16* xt  = pb;     // xT dead before pb written (by dwconv_ln)
    __nv_bfloat16* f1b = qkvb;   // f1b dead before qkv GEMM writes

    cudaFuncSetAttribute(tail_kernel,
                         cudaFuncAttributeMaxDynamicSharedMemorySize, TAIL_SMEM);
    cudaFuncSetAttribute(attention_kernel,
                         cudaFuncAttributeMaxDynamicSharedMemorySize, ATT_SMEM);

    zero_loss_kernel<<<1, 1>>>(loss);

    // weight prep (tiny)
    convert_w_kernel<<<(192*192 + 255) / 256, 256>>>(w_pre1, wtpre, 192*192);
    transpose_w_kernel<<<(192*576 + 255) / 256, 256>>>(w_qkv, wtq, 192, 576);
    transpose_w_kernel<<<(192*768 + 255) / 256, 256>>>(w_g1, wtg1, 192, 768);
    transpose_w_kernel<<<(768*192 + 255) / 256, 256>>>(w_g2, wtg2, 768, 192);
    transpose_w_kernel<<<(192*192 + 255) / 256, 256>>>(w_proj, wtp, 192, 192);
    transpose_w_kernel<<<(192*192 + 255) / 256, 256>>>(w_rec, wtr, 192, 192);

    // 0) x -> NHWC bf16
    transpose_x_kernel<<<dim3(HW / 32, CDIM / 32, BATCH), 256>>>(x, xt);

    // 1) 1x1 conv as HMMA GEMM
    hmma_gemm<E_BIASN><<<dim3(2, NTOK / 128), 256>>>(
        xt, 192, wtpre, 192, b_pre1, f1b, 192);

    // 2+3) depthwise 3x3 + LN + window partition -> pb (bf16)
    dwconv_ln_kernel<<<NTOK, 192>>>(f1b, w_dw, b_dw, ln_g, ln_b, pb);

    // 4) qkv = pb @ w_qkv + b
    hmma_gemm<E_BIASN><<<dim3(6, NTOK / 128), 256>>>(
        pb, 192, wtq, 192, b_qkv, qkvb, 576);

    // 5) windowed attention (HMMA) -> attnb bf16
    attention_kernel<<<NWIN, 768, ATT_SMEM>>>(qkvb, attnb);

    // 6) h = gelu(v @ w_g1 + b_g1)
    hmma_gemm<E_GELU><<<dim3(8, NTOK / 128), 256>>>(
        qkvb + 384, 576, wtg1, 192, b_g1, hb, 768);

    // 7-10) fused tail: g2 GEMM + gate + proj + rec/loss + reverse/residual
    tail_kernel<<<NWIN, 256, TAIL_SMEM>>>(
        hb, wtg2, b_g2, attnb, wtp, b_proj, wtr, b_rec, pb, x, out, loss);

    // 11) loss scalar
    if ((size_t)out_size > OUT_MAIN)
        finalize_loss_kernel<<<1, 1>>>(loss, out, (size_t)out_size - 1);
}